// round 1
// baseline (speedup 1.0000x reference)
#include <cuda_runtime.h>

// ---------------------------------------------------------------------------
// Residual Vector Quantization (Encodec-style), 8 layers, fused per-layer
// GEMM(+argmin)+update kernel using packed fp32 FFMA2 (fma.rn.f32x2).
//
// Shapes: x [16,256,4096] f32, codebooks [8,1024,256] f32.
// Output (flat f32): quantized [16,256,4096] | codes [8,16,4096] | loss [1]
// ---------------------------------------------------------------------------

namespace {
constexpr int Bb    = 16;
constexpr int Dd    = 256;
constexpr int Tt    = 4096;
constexpr int NQ    = 8;
constexpr int NBINS = 1024;
constexpr int NVEC  = Bb * Tt;        // 65536 vectors
constexpr int MTILE = 128;
constexpr int GRID_L = NVEC / MTILE;  // 512 CTAs per layer kernel

// shared-memory layout (in floats)
constexpr int AS_STRIDE = 132;                     // 256 x 132 (padded) A tile, [k][m]
constexpr int AS_FLOATS = 256 * AS_STRIDE;         // 33792
constexpr int BS_STRIDE = 260;                     // 16 x 260: B duplicated pairs (b,b)
constexpr int BS_FLOATS = 2 * 16 * BS_STRIDE;      // 8320 (double-buffered)
constexpr int SIDX_OFF  = AS_FLOATS + BS_FLOATS;   // 128 ints
constexpr int WLOSS_OFF = SIDX_OFF + 128;          // 8 floats (+pad)
constexpr int SMEM_FLOATS = WLOSS_OFF + 16;
constexpr size_t SMEM_BYTES = (size_t)SMEM_FLOATS * sizeof(float);  // ~169 KB
}

// ---------------- device scratch (static; no runtime allocation) -----------
__device__ __align__(16) float g_resid[(size_t)NVEC * Dd];   // 64 MB residual [n][d]
__device__ __align__(16) float g_rr[NVEC];                   // per-row ||r||^2
__device__ __align__(16) float g_cc[NQ * NBINS];             // per-code ||c||^2
__device__ __align__(16) float g_losspart[NQ * GRID_L];      // per-layer per-block loss partials

// ---------------- packed f32x2 helpers --------------------------------------
__device__ __forceinline__ unsigned long long pack2(float lo, float hi) {
    unsigned long long r;
    asm("mov.b64 %0, {%1, %2};" : "=l"(r) : "f"(lo), "f"(hi));
    return r;
}
__device__ __forceinline__ float2 unpack2(unsigned long long v) {
    float2 r;
    asm("mov.b64 {%0, %1}, %2;" : "=f"(r.x), "=f"(r.y) : "l"(v));
    return r;
}
__device__ __forceinline__ void fma2(unsigned long long& d,
                                     unsigned long long a,
                                     unsigned long long b) {
    asm("fma.rn.f32x2 %0, %1, %2, %0;" : "+l"(d) : "l"(a), "l"(b));
}

// ---------------- kernel: transpose x[B,D,T] -> resid[n][d] -----------------
__global__ void transpose_in_kernel(const float* __restrict__ x) {
    __shared__ float tile[32][33];
    const int b  = blockIdx.z;
    const int d0 = blockIdx.y * 32;
    const int t0 = blockIdx.x * 32;
    const int tx = threadIdx.x, ty = threadIdx.y;
    const float* xb = x + (size_t)b * Dd * Tt;
#pragma unroll
    for (int i = 0; i < 32; i += 8)
        tile[ty + i][tx] = xb[(size_t)(d0 + ty + i) * Tt + t0 + tx];
    __syncthreads();
#pragma unroll
    for (int i = 0; i < 32; i += 8) {
        const int t = t0 + ty + i;
        g_resid[(size_t)(b * Tt + t) * Dd + d0 + tx] = tile[tx][ty + i];
    }
}

// ---------------- kernel: row squared norms of residual ---------------------
__global__ void rownorm_kernel() {
    const int row  = blockIdx.x * 8 + (threadIdx.x >> 5);
    const int lane = threadIdx.x & 31;
    const float* r = g_resid + (size_t)row * Dd;
    float s = 0.f;
#pragma unroll
    for (int i = 0; i < 8; i++) { float v = r[i * 32 + lane]; s = fmaf(v, v, s); }
#pragma unroll
    for (int o = 16; o; o >>= 1) s += __shfl_down_sync(0xffffffffu, s, o);
    if (!lane) g_rr[row] = s;
}

// ---------------- kernel: codebook squared norms ----------------------------
__global__ void codenorm_kernel(const float* __restrict__ cbs) {
    const int c    = blockIdx.x * 8 + (threadIdx.x >> 5);  // 0..8191
    const int lane = threadIdx.x & 31;
    const float* r = cbs + (size_t)c * Dd;
    float s = 0.f;
#pragma unroll
    for (int i = 0; i < 8; i++) { float v = r[i * 32 + lane]; s = fmaf(v, v, s); }
#pragma unroll
    for (int o = 16; o; o >>= 1) s += __shfl_down_sync(0xffffffffu, s, o);
    if (!lane) g_cc[c] = s;
}

// ---------------- kernel: one RVQ layer (fused GEMM+argmin+update) ----------
__global__ __launch_bounds__(256, 1)
void rvq_layer_kernel(const float* __restrict__ cb,   // this layer's codebook [1024][256]
                      int layer,
                      float* __restrict__ codes_out)  // base of codes region or null
{
    extern __shared__ float sm[];
    float* As   = sm;                         // [k=256][m=128] residual tile
    float* Bsd  = sm + AS_FLOATS;             // [2][k=16][2*j=256] duplicated (b,b)
    float* sbest  = Bsd;                      // overlap after mainloop: [16][128]
    int*   sbestj = (int*)(Bsd + 2048);       // [16][128]
    int*   sidx   = (int*)(sm + SIDX_OFF);    // [128]
    float* wloss  = sm + WLOSS_OFF;           // [8]

    const int tid = threadIdx.x;
    const int tx  = tid & 15;     // j direction (16 threads x 8 j = 128)
    const int ty  = tid >> 4;     // m direction (16 threads x 8 m = 128)
    const int n0  = blockIdx.x * MTILE;
    const float* ccL = g_cc + layer * NBINS;

    // ---- load A tile: As[k][m] = resid[(n0+m)*256 + k], k = tid ----
    {
        const float* rp = g_resid + (size_t)n0 * Dd + tid;
        float* ap = As + tid * AS_STRIDE;
#pragma unroll 8
        for (int m = 0; m < MTILE; m++) ap[m] = rp[(size_t)m * Dd];
    }
    // per-thread row norms (8 m rows)
    float rreg[8];
#pragma unroll
    for (int r = 0; r < 8; r++) rreg[r] = g_rr[n0 + ty * 8 + r];

    float best[8];
    int   bestj[8];
#pragma unroll
    for (int r = 0; r < 8; r++) { best[r] = 3.402823466e38f; bestj[r] = 0; }

    __syncthreads();

    // ---- main loop: 8 j-tiles of 128 codes each ----
#pragma unroll 1
    for (int jit = 0; jit < 8; jit++) {
        const int j0 = jit * 128;

        unsigned long long acc[4][8];
#pragma unroll
        for (int mp = 0; mp < 4; mp++)
#pragma unroll
            for (int p = 0; p < 8; p++) acc[mp][p] = 0ull;

        // prologue: load k-tile 0 into buffer 0 (duplicated pairs)
        float v[8];
#pragma unroll
        for (int i = 0; i < 8; i++)
            v[i] = cb[(size_t)(j0 + ty + 16 * i) * Dd + tx];
#pragma unroll
        for (int i = 0; i < 8; i++)
            *(float2*)&Bsd[tx * BS_STRIDE + 2 * (ty + 16 * i)] = make_float2(v[i], v[i]);
        __syncthreads();

#pragma unroll 1
        for (int kt = 0; kt < 16; kt++) {
            const int cur = kt & 1;
            if (kt < 15) {
#pragma unroll
                for (int i = 0; i < 8; i++)
                    v[i] = cb[(size_t)(j0 + ty + 16 * i) * Dd + (kt + 1) * 16 + tx];
            }
            const float* asb = As + (kt * 16) * AS_STRIDE + ty * 8;
            const float* bsb = Bsd + cur * 16 * BS_STRIDE + tx * 16;
#pragma unroll
            for (int kk = 0; kk < 16; kk++) {
                const float2 a0 = *(const float2*)(asb + kk * AS_STRIDE + 0);
                const float2 a1 = *(const float2*)(asb + kk * AS_STRIDE + 2);
                const float2 a2 = *(const float2*)(asb + kk * AS_STRIDE + 4);
                const float2 a3 = *(const float2*)(asb + kk * AS_STRIDE + 6);
                const float4 b0 = *(const float4*)(bsb + kk * BS_STRIDE + 0);
                const float4 b1 = *(const float4*)(bsb + kk * BS_STRIDE + 4);
                const float4 b2 = *(const float4*)(bsb + kk * BS_STRIDE + 8);
                const float4 b3 = *(const float4*)(bsb + kk * BS_STRIDE + 12);
                unsigned long long au[4];
                au[0] = pack2(a0.x, a0.y); au[1] = pack2(a1.x, a1.y);
                au[2] = pack2(a2.x, a2.y); au[3] = pack2(a3.x, a3.y);
                unsigned long long bu[8];
                bu[0] = pack2(b0.x, b0.y); bu[1] = pack2(b0.z, b0.w);
                bu[2] = pack2(b1.x, b1.y); bu[3] = pack2(b1.z, b1.w);
                bu[4] = pack2(b2.x, b2.y); bu[5] = pack2(b2.z, b2.w);
                bu[6] = pack2(b3.x, b3.y); bu[7] = pack2(b3.z, b3.w);
#pragma unroll
                for (int mp = 0; mp < 4; mp++)
#pragma unroll
                    for (int p = 0; p < 8; p++)
                        fma2(acc[mp][p], au[mp], bu[p]);
            }
            if (kt < 15) {
                const int nb = cur ^ 1;
#pragma unroll
                for (int i = 0; i < 8; i++)
                    *(float2*)&Bsd[nb * 16 * BS_STRIDE + tx * BS_STRIDE + 2 * (ty + 16 * i)] =
                        make_float2(v[i], v[i]);
            }
            __syncthreads();
        }

        // epilogue: distances + running argmin (j ascending => first-min wins)
        float ccv[8];
        {
            const float4 c0 = *(const float4*)(ccL + j0 + tx * 8);
            const float4 c1 = *(const float4*)(ccL + j0 + tx * 8 + 4);
            ccv[0] = c0.x; ccv[1] = c0.y; ccv[2] = c0.z; ccv[3] = c0.w;
            ccv[4] = c1.x; ccv[5] = c1.y; ccv[6] = c1.z; ccv[7] = c1.w;
        }
#pragma unroll
        for (int p = 0; p < 8; p++) {
            const int j = j0 + tx * 8 + p;
#pragma unroll
            for (int mp = 0; mp < 4; mp++) {
                const float2 d2 = unpack2(acc[mp][p]);
                // mirrors jax: rr - 2*dot (2*dot exact => single rounding) then + cc
                const float dist0 = fmaf(-2.f, d2.x, rreg[2 * mp])     + ccv[p];
                const float dist1 = fmaf(-2.f, d2.y, rreg[2 * mp + 1]) + ccv[p];
                if (dist0 < best[2 * mp])     { best[2 * mp]     = dist0; bestj[2 * mp]     = j; }
                if (dist1 < best[2 * mp + 1]) { best[2 * mp + 1] = dist1; bestj[2 * mp + 1] = j; }
            }
        }
    }

    // ---- cross-thread argmin reduction (16 tx slots per m row) ----
#pragma unroll
    for (int r = 0; r < 8; r++) {
        sbest[tx * 128 + ty * 8 + r]  = best[r];
        sbestj[tx * 128 + ty * 8 + r] = bestj[r];
    }
    __syncthreads();
    if (tid < 128) {
        float bv = 3.402823466e38f;
        int   bj = 0x7fffffff;
#pragma unroll
        for (int t2 = 0; t2 < 16; t2++) {
            const float vv = sbest[t2 * 128 + tid];
            const int   jj = sbestj[t2 * 128 + tid];
            if (vv < bv || (vv == bv && jj < bj)) { bv = vv; bj = jj; }
        }
        sidx[tid] = bj;
    }
    __syncthreads();

    // ---- fused update: resid -= cb[idx]; new row norms; codes; loss ----
    const int wid = tid >> 5, lane = tid & 31;
    float wl = 0.f;
    for (int m = wid; m < MTILE; m += 8) {
        const int j = sidx[m];
        const float* q = cb + (size_t)j * Dd;
        float* rout = g_resid + (size_t)(n0 + m) * Dd;
        float s = 0.f;
#pragma unroll
        for (int i = 0; i < 8; i++) {
            const int d = i * 32 + lane;
            const float rn = As[d * AS_STRIDE + m] - q[d];
            rout[d] = rn;
            s = fmaf(rn, rn, s);
        }
#pragma unroll
        for (int o = 16; o; o >>= 1) s += __shfl_down_sync(0xffffffffu, s, o);
        if (!lane) {
            g_rr[n0 + m] = s;     // next layer's row norm
            wl += s;              // loss = ||r_new||^2 (since q - r_old = -r_new)
            if (codes_out) codes_out[(size_t)layer * NVEC + n0 + m] = (float)j;
        }
    }
    if (!lane) wloss[wid] = wl;
    __syncthreads();
    if (tid == 0) {
        float t = 0.f;
#pragma unroll
        for (int w = 0; w < 8; w++) t += wloss[w];
        g_losspart[layer * GRID_L + blockIdx.x] = t;
    }
}

// ---------------- kernel: quantized = x - resid_final (transposed), + loss --
__global__ void finalize_kernel(const float* __restrict__ x,
                                float* __restrict__ out,
                                float* __restrict__ loss_dst) {
    __shared__ float tile[32][33];
    const int b  = blockIdx.z;
    const int d0 = blockIdx.y * 32;
    const int t0 = blockIdx.x * 32;
    const int tx = threadIdx.x, ty = threadIdx.y;
#pragma unroll
    for (int i = 0; i < 32; i += 8)
        tile[ty + i][tx] = g_resid[(size_t)(b * Tt + t0 + ty + i) * Dd + d0 + tx];
    __syncthreads();
#pragma unroll
    for (int i = 0; i < 32; i += 8) {
        const size_t idx = (size_t)b * Dd * Tt + (size_t)(d0 + ty + i) * Tt + t0 + tx;
        out[idx] = x[idx] - tile[tx][ty + i];
    }
    // one warp computes the scalar loss (deterministic serial/warp sum)
    if (loss_dst && blockIdx.x == 0 && blockIdx.y == 0 && blockIdx.z == 0 && ty == 0) {
        double s = 0.0;
        for (int i = tx; i < NQ * GRID_L; i += 32) s += (double)g_losspart[i];
#pragma unroll
        for (int o = 16; o; o >>= 1) s += __shfl_down_sync(0xffffffffu, s, o);
        if (tx == 0)
            *loss_dst = (float)(s / ((double)NQ * (double)NVEC * (double)Dd));
    }
}

// ---------------- launch -----------------------------------------------------
extern "C" void kernel_launch(void* const* d_in, const int* in_sizes, int n_in,
                              void* d_out, int out_size) {
    const float* x   = (const float*)d_in[0];   // [16,256,4096]
    const float* cbs = (const float*)d_in[1];   // [8,1024,256]
    float* out = (float*)d_out;

    const long long QN = (long long)Bb * Dd * Tt;   // 16777216
    const long long CN = (long long)NQ * Bb * Tt;   // 524288
    float* codes = ((long long)out_size >= QN + CN) ? out + QN : nullptr;
    float* lossp = ((long long)out_size >= QN + CN + 1) ? out + QN + CN : nullptr;

    cudaFuncSetAttribute(rvq_layer_kernel,
                         cudaFuncAttributeMaxDynamicSharedMemorySize,
                         (int)SMEM_BYTES);

    transpose_in_kernel<<<dim3(Tt / 32, Dd / 32, Bb), dim3(32, 8)>>>(x);
    rownorm_kernel<<<NVEC / 8, 256>>>();
    codenorm_kernel<<<NQ * NBINS / 8, 256>>>(cbs);
    for (int l = 0; l < NQ; l++) {
        rvq_layer_kernel<<<GRID_L, 256, SMEM_BYTES>>>(
            cbs + (size_t)l * NBINS * Dd, l, codes);
    }
    finalize_kernel<<<dim3(Tt / 32, Dd / 32, Bb), dim3(32, 8)>>>(x, out, lossp);
}

// round 2
// speedup vs baseline: 2.7018x; 2.7018x over previous
#include <cuda_runtime.h>

// ---------------------------------------------------------------------------
// Residual Vector Quantization (Encodec-style), 8 layers, fused per-layer
// GEMM(+argmin)+update kernel using packed fp32 FFMA2 (fma.rn.f32x2).
// R1 -> R2: conflict-free B smem layout (16-float groups padded to 20),
//           A stride 132 -> 134 (fewer writer store conflicts).
// ---------------------------------------------------------------------------

namespace {
constexpr int Bb    = 16;
constexpr int Dd    = 256;
constexpr int Tt    = 4096;
constexpr int NQ    = 8;
constexpr int NBINS = 1024;
constexpr int NVEC  = Bb * Tt;        // 65536 vectors
constexpr int MTILE = 128;
constexpr int GRID_L = NVEC / MTILE;  // 512 CTAs per layer kernel

// shared-memory layout (in floats)
constexpr int AS_STRIDE = 134;                     // 256 x 134 (padded) A tile, [k][m]
constexpr int AS_FLOATS = 256 * AS_STRIDE;         // 34304
// B: per k-row, 16 groups; group g = duplicated pairs for j = g*8..g*8+7
//    group occupies 16 floats, padded to 20 (bank-conflict-free float4 reads)
constexpr int BS_GROUP  = 20;
constexpr int BS_ROW    = 328;                     // 16*20=320, pad to 328
constexpr int BS_BUF    = 16 * BS_ROW;             // 5248 floats per k-chunk buffer
constexpr int BS_FLOATS = 2 * BS_BUF;              // 10496 (double-buffered)
constexpr int SIDX_OFF  = AS_FLOATS + BS_FLOATS;   // 44800: 128 ints
constexpr int WLOSS_OFF = SIDX_OFF + 128;          // 8 floats (+pad)
constexpr int SMEM_FLOATS = WLOSS_OFF + 16;
constexpr size_t SMEM_BYTES = (size_t)SMEM_FLOATS * sizeof(float);  // ~180 KB
}

// ---------------- device scratch (static; no runtime allocation) -----------
__device__ __align__(16) float g_resid[(size_t)NVEC * Dd];   // 64 MB residual [n][d]
__device__ __align__(16) float g_rr[NVEC];                   // per-row ||r||^2
__device__ __align__(16) float g_cc[NQ * NBINS];             // per-code ||c||^2
__device__ __align__(16) float g_losspart[NQ * GRID_L];      // per-layer per-block loss partials

// ---------------- packed f32x2 helpers --------------------------------------
__device__ __forceinline__ unsigned long long pack2(float lo, float hi) {
    unsigned long long r;
    asm("mov.b64 %0, {%1, %2};" : "=l"(r) : "f"(lo), "f"(hi));
    return r;
}
__device__ __forceinline__ float2 unpack2(unsigned long long v) {
    float2 r;
    asm("mov.b64 {%0, %1}, %2;" : "=f"(r.x), "=f"(r.y) : "l"(v));
    return r;
}
__device__ __forceinline__ void fma2(unsigned long long& d,
                                     unsigned long long a,
                                     unsigned long long b) {
    asm("fma.rn.f32x2 %0, %1, %2, %0;" : "+l"(d) : "l"(a), "l"(b));
}

// ---------------- kernel: transpose x[B,D,T] -> resid[n][d] -----------------
__global__ void transpose_in_kernel(const float* __restrict__ x) {
    __shared__ float tile[32][33];
    const int b  = blockIdx.z;
    const int d0 = blockIdx.y * 32;
    const int t0 = blockIdx.x * 32;
    const int tx = threadIdx.x, ty = threadIdx.y;
    const float* xb = x + (size_t)b * Dd * Tt;
#pragma unroll
    for (int i = 0; i < 32; i += 8)
        tile[ty + i][tx] = xb[(size_t)(d0 + ty + i) * Tt + t0 + tx];
    __syncthreads();
#pragma unroll
    for (int i = 0; i < 32; i += 8) {
        const int t = t0 + ty + i;
        g_resid[(size_t)(b * Tt + t) * Dd + d0 + tx] = tile[tx][ty + i];
    }
}

// ---------------- kernel: row squared norms of residual ---------------------
__global__ void rownorm_kernel() {
    const int row  = blockIdx.x * 8 + (threadIdx.x >> 5);
    const int lane = threadIdx.x & 31;
    const float* r = g_resid + (size_t)row * Dd;
    float s = 0.f;
#pragma unroll
    for (int i = 0; i < 8; i++) { float v = r[i * 32 + lane]; s = fmaf(v, v, s); }
#pragma unroll
    for (int o = 16; o; o >>= 1) s += __shfl_down_sync(0xffffffffu, s, o);
    if (!lane) g_rr[row] = s;
}

// ---------------- kernel: codebook squared norms ----------------------------
__global__ void codenorm_kernel(const float* __restrict__ cbs) {
    const int c    = blockIdx.x * 8 + (threadIdx.x >> 5);  // 0..8191
    const int lane = threadIdx.x & 31;
    const float* r = cbs + (size_t)c * Dd;
    float s = 0.f;
#pragma unroll
    for (int i = 0; i < 8; i++) { float v = r[i * 32 + lane]; s = fmaf(v, v, s); }
#pragma unroll
    for (int o = 16; o; o >>= 1) s += __shfl_down_sync(0xffffffffu, s, o);
    if (!lane) g_cc[c] = s;
}

// ---------------- kernel: one RVQ layer (fused GEMM+argmin+update) ----------
__global__ __launch_bounds__(256, 1)
void rvq_layer_kernel(const float* __restrict__ cb,   // this layer's codebook [1024][256]
                      int layer,
                      float* __restrict__ codes_out)  // base of codes region or null
{
    extern __shared__ float sm[];
    float* As   = sm;                         // [k=256][m=128] residual tile
    float* Bsd  = sm + AS_FLOATS;             // [2][k=16][16 groups x 20] duplicated (b,b)
    float* sbest  = Bsd;                      // overlap after mainloop: [16][128]
    int*   sbestj = (int*)(Bsd + 2048);       // [16][128]
    int*   sidx   = (int*)(sm + SIDX_OFF);    // [128]
    float* wloss  = sm + WLOSS_OFF;           // [8]

    const int tid = threadIdx.x;
    const int tx  = tid & 15;     // j direction (16 threads x 8 j = 128)
    const int ty  = tid >> 4;     // m direction (16 threads x 8 m = 128)
    const int n0  = blockIdx.x * MTILE;
    const float* ccL = g_cc + layer * NBINS;

    // B-writer mapping: thread handles k-column (tid&15), j-group (tid>>4)
    const int wk = tid & 15;      // k within 16-chunk
    const int wj = tid >> 4;      // j-group 0..15 (8 j's each)

    // ---- load A tile: As[k][m] = resid[(n0+m)*256 + k], k = tid ----
    {
        const float* rp = g_resid + (size_t)n0 * Dd + tid;
        float* ap = As + tid * AS_STRIDE;
#pragma unroll 8
        for (int m = 0; m < MTILE; m++) ap[m] = rp[(size_t)m * Dd];
    }
    // per-thread row norms (8 m rows)
    float rreg[8];
#pragma unroll
    for (int r = 0; r < 8; r++) rreg[r] = g_rr[n0 + ty * 8 + r];

    float best[8];
    int   bestj[8];
#pragma unroll
    for (int r = 0; r < 8; r++) { best[r] = 3.402823466e38f; bestj[r] = 0; }

    __syncthreads();

    // ---- main loop: 8 j-tiles of 128 codes each ----
#pragma unroll 1
    for (int jit = 0; jit < 8; jit++) {
        const int j0 = jit * 128;

        unsigned long long acc[4][8];
#pragma unroll
        for (int mp = 0; mp < 4; mp++)
#pragma unroll
            for (int p = 0; p < 8; p++) acc[mp][p] = 0ull;

        // prologue: load k-tile 0 into buffer 0 (duplicated pairs, padded groups)
        float v[8];
#pragma unroll
        for (int u = 0; u < 8; u++)
            v[u] = cb[(size_t)(j0 + wj * 8 + u) * Dd + wk];
        {
            float* dst = Bsd + wk * BS_ROW + wj * BS_GROUP;
            *(float4*)(dst + 0)  = make_float4(v[0], v[0], v[1], v[1]);
            *(float4*)(dst + 4)  = make_float4(v[2], v[2], v[3], v[3]);
            *(float4*)(dst + 8)  = make_float4(v[4], v[4], v[5], v[5]);
            *(float4*)(dst + 12) = make_float4(v[6], v[6], v[7], v[7]);
        }
        __syncthreads();

#pragma unroll 1
        for (int kt = 0; kt < 16; kt++) {
            const int cur = kt & 1;
            if (kt < 15) {
#pragma unroll
                for (int u = 0; u < 8; u++)
                    v[u] = cb[(size_t)(j0 + wj * 8 + u) * Dd + (kt + 1) * 16 + wk];
            }
            const float* asb = As + (kt * 16) * AS_STRIDE + ty * 8;
            const float* bsb = Bsd + cur * BS_BUF + tx * BS_GROUP;
#pragma unroll
            for (int kk = 0; kk < 16; kk++) {
                const float2 a0 = *(const float2*)(asb + kk * AS_STRIDE + 0);
                const float2 a1 = *(const float2*)(asb + kk * AS_STRIDE + 2);
                const float2 a2 = *(const float2*)(asb + kk * AS_STRIDE + 4);
                const float2 a3 = *(const float2*)(asb + kk * AS_STRIDE + 6);
                const float4 b0 = *(const float4*)(bsb + kk * BS_ROW + 0);
                const float4 b1 = *(const float4*)(bsb + kk * BS_ROW + 4);
                const float4 b2 = *(const float4*)(bsb + kk * BS_ROW + 8);
                const float4 b3 = *(const float4*)(bsb + kk * BS_ROW + 12);
                unsigned long long au[4];
                au[0] = pack2(a0.x, a0.y); au[1] = pack2(a1.x, a1.y);
                au[2] = pack2(a2.x, a2.y); au[3] = pack2(a3.x, a3.y);
                unsigned long long bu[8];
                bu[0] = pack2(b0.x, b0.y); bu[1] = pack2(b0.z, b0.w);
                bu[2] = pack2(b1.x, b1.y); bu[3] = pack2(b1.z, b1.w);
                bu[4] = pack2(b2.x, b2.y); bu[5] = pack2(b2.z, b2.w);
                bu[6] = pack2(b3.x, b3.y); bu[7] = pack2(b3.z, b3.w);
#pragma unroll
                for (int mp = 0; mp < 4; mp++)
#pragma unroll
                    for (int p = 0; p < 8; p++)
                        fma2(acc[mp][p], au[mp], bu[p]);
            }
            if (kt < 15) {
                float* dst = Bsd + (cur ^ 1) * BS_BUF + wk * BS_ROW + wj * BS_GROUP;
                *(float4*)(dst + 0)  = make_float4(v[0], v[0], v[1], v[1]);
                *(float4*)(dst + 4)  = make_float4(v[2], v[2], v[3], v[3]);
                *(float4*)(dst + 8)  = make_float4(v[4], v[4], v[5], v[5]);
                *(float4*)(dst + 12) = make_float4(v[6], v[6], v[7], v[7]);
            }
            __syncthreads();
        }

        // epilogue: distances + running argmin (j ascending => first-min wins)
        float ccv[8];
        {
            const float4 c0 = *(const float4*)(ccL + j0 + tx * 8);
            const float4 c1 = *(const float4*)(ccL + j0 + tx * 8 + 4);
            ccv[0] = c0.x; ccv[1] = c0.y; ccv[2] = c0.z; ccv[3] = c0.w;
            ccv[4] = c1.x; ccv[5] = c1.y; ccv[6] = c1.z; ccv[7] = c1.w;
        }
#pragma unroll
        for (int p = 0; p < 8; p++) {
            const int j = j0 + tx * 8 + p;
#pragma unroll
            for (int mp = 0; mp < 4; mp++) {
                const float2 d2 = unpack2(acc[mp][p]);
                // mirrors jax: rr - 2*dot (2*dot exact => single rounding) then + cc
                const float dist0 = fmaf(-2.f, d2.x, rreg[2 * mp])     + ccv[p];
                const float dist1 = fmaf(-2.f, d2.y, rreg[2 * mp + 1]) + ccv[p];
                if (dist0 < best[2 * mp])     { best[2 * mp]     = dist0; bestj[2 * mp]     = j; }
                if (dist1 < best[2 * mp + 1]) { best[2 * mp + 1] = dist1; bestj[2 * mp + 1] = j; }
            }
        }
    }

    // ---- cross-thread argmin reduction (16 tx slots per m row) ----
#pragma unroll
    for (int r = 0; r < 8; r++) {
        sbest[tx * 128 + ty * 8 + r]  = best[r];
        sbestj[tx * 128 + ty * 8 + r] = bestj[r];
    }
    __syncthreads();
    if (tid < 128) {
        float bv = 3.402823466e38f;
        int   bj = 0x7fffffff;
#pragma unroll
        for (int t2 = 0; t2 < 16; t2++) {
            const float vv = sbest[t2 * 128 + tid];
            const int   jj = sbestj[t2 * 128 + tid];
            if (vv < bv || (vv == bv && jj < bj)) { bv = vv; bj = jj; }
        }
        sidx[tid] = bj;
    }
    __syncthreads();

    // ---- fused update: resid -= cb[idx]; new row norms; codes; loss ----
    const int wid = tid >> 5, lane = tid & 31;
    float wl = 0.f;
    for (int m = wid; m < MTILE; m += 8) {
        const int j = sidx[m];
        const float* q = cb + (size_t)j * Dd;
        float* rout = g_resid + (size_t)(n0 + m) * Dd;
        float s = 0.f;
#pragma unroll
        for (int i = 0; i < 8; i++) {
            const int d = i * 32 + lane;
            const float rn = As[d * AS_STRIDE + m] - q[d];
            rout[d] = rn;
            s = fmaf(rn, rn, s);
        }
#pragma unroll
        for (int o = 16; o; o >>= 1) s += __shfl_down_sync(0xffffffffu, s, o);
        if (!lane) {
            g_rr[n0 + m] = s;     // next layer's row norm
            wl += s;              // loss = ||r_new||^2 (since q - r_old = -r_new)
            if (codes_out) codes_out[(size_t)layer * NVEC + n0 + m] = (float)j;
        }
    }
    if (!lane) wloss[wid] = wl;
    __syncthreads();
    if (tid == 0) {
        float t = 0.f;
#pragma unroll
        for (int w = 0; w < 8; w++) t += wloss[w];
        g_losspart[layer * GRID_L + blockIdx.x] = t;
    }
}

// ---------------- kernel: quantized = x - resid_final (transposed), + loss --
__global__ void finalize_kernel(const float* __restrict__ x,
                                float* __restrict__ out,
                                float* __restrict__ loss_dst) {
    __shared__ float tile[32][33];
    const int b  = blockIdx.z;
    const int d0 = blockIdx.y * 32;
    const int t0 = blockIdx.x * 32;
    const int tx = threadIdx.x, ty = threadIdx.y;
#pragma unroll
    for (int i = 0; i < 32; i += 8)
        tile[ty + i][tx] = g_resid[(size_t)(b * Tt + t0 + ty + i) * Dd + d0 + tx];
    __syncthreads();
#pragma unroll
    for (int i = 0; i < 32; i += 8) {
        const size_t idx = (size_t)b * Dd * Tt + (size_t)(d0 + ty + i) * Tt + t0 + tx;
        out[idx] = x[idx] - tile[tx][ty + i];
    }
    // one warp computes the scalar loss (deterministic serial/warp sum)
    if (loss_dst && blockIdx.x == 0 && blockIdx.y == 0 && blockIdx.z == 0 && ty == 0) {
        double s = 0.0;
        for (int i = tx; i < NQ * GRID_L; i += 32) s += (double)g_losspart[i];
#pragma unroll
        for (int o = 16; o; o >>= 1) s += __shfl_down_sync(0xffffffffu, s, o);
        if (tx == 0)
            *loss_dst = (float)(s / ((double)NQ * (double)NVEC * (double)Dd));
    }
}

// ---------------- launch -----------------------------------------------------
extern "C" void kernel_launch(void* const* d_in, const int* in_sizes, int n_in,
                              void* d_out, int out_size) {
    const float* x   = (const float*)d_in[0];   // [16,256,4096]
    const float* cbs = (const float*)d_in[1];   // [8,1024,256]
    float* out = (float*)d_out;

    const long long QN = (long long)Bb * Dd * Tt;   // 16777216
    const long long CN = (long long)NQ * Bb * Tt;   // 524288
    float* codes = ((long long)out_size >= QN + CN) ? out + QN : nullptr;
    float* lossp = ((long long)out_size >= QN + CN + 1) ? out + QN + CN : nullptr;

    cudaFuncSetAttribute(rvq_layer_kernel,
                         cudaFuncAttributeMaxDynamicSharedMemorySize,
                         (int)SMEM_BYTES);

    transpose_in_kernel<<<dim3(Tt / 32, Dd / 32, Bb), dim3(32, 8)>>>(x);
    rownorm_kernel<<<NVEC / 8, 256>>>();
    codenorm_kernel<<<NQ * NBINS / 8, 256>>>(cbs);
    for (int l = 0; l < NQ; l++) {
        rvq_layer_kernel<<<GRID_L, 256, SMEM_BYTES>>>(
            cbs + (size_t)l * NBINS * Dd, l, codes);
    }
    finalize_kernel<<<dim3(Tt / 32, Dd / 32, Bb), dim3(32, 8)>>>(x, out, lossp);
}